// round 3
// baseline (speedup 1.0000x reference)
#include <cuda_runtime.h>
#include <cstddef>

#define SEQ   512
#define BATCH 4096
#define INDIM 9
#define HID   64
#define OUTD  10
#define NTH   256
#define CSCALE 2.885390081777927f   // 2/ln2, folded into weights for tanh

// shared memory float offsets
#define O_HIST  0                          // (SEQ+1)*HID : xw1 -> h2 history; row SEQ = dummy
#define O_XS    (O_HIST + (SEQ+1)*HID)     // SEQ*INDIM
#define O_H1    (O_XS + SEQ*INDIM)         // 2*HID
#define O_H2    (O_H1 + 2*HID)             // 2*HID
#define O_ZROW  (O_H2 + 2*HID)             // HID  (zeros, layer2 "xw" source)
#define O_TRASH (O_ZROW + HID)             // HID  (write sink)
#define O_WFC   (O_TRASH + HID)            // OUTD*HID
#define O_BFC   (O_WFC + OUTD*HID)         // OUTD (+pad)
#define SM_FLOATS (O_BFC + 16)
#define SM_BYTES  (SM_FLOATS * 4)

typedef unsigned long long ull;

__device__ __forceinline__ ull ffma2(ull a, ull b, ull c) {
    ull d; asm("fma.rn.f32x2 %0, %1, %2, %3;" : "=l"(d) : "l"(a), "l"(b), "l"(c));
    return d;
}
__device__ __forceinline__ ull fadd2(ull a, ull b) {
    ull d; asm("add.rn.f32x2 %0, %1, %2;" : "=l"(d) : "l"(a), "l"(b));
    return d;
}
__device__ __forceinline__ float f2sum(ull a) {
    float2 f = *reinterpret_cast<float2*>(&a);
    return f.x + f.y;
}
__device__ __forceinline__ ull pack2(float x, float y) {
    ull r; asm("mov.b64 %0, {%1,%2};" : "=l"(r) : "f"(x), "f"(y));
    return r;
}

// 32-long half dot: w (16 x f32x2 regs) . h (32 floats in smem), 4 indep chains
__device__ __forceinline__ ull hdot(const ull* w, const float* h) {
    const ulonglong2* hp = reinterpret_cast<const ulonglong2*>(h);
    ull a0 = 0ull, a1 = 0ull, a2 = 0ull, a3 = 0ull;
    #pragma unroll
    for (int q = 0; q < 4; ++q) {
        ulonglong2 v0 = hp[2*q], v1 = hp[2*q+1];
        a0 = ffma2(v0.x, w[4*q+0], a0);
        a1 = ffma2(v0.y, w[4*q+1], a1);
        a2 = ffma2(v1.x, w[4*q+2], a2);
        a3 = ffma2(v1.y, w[4*q+3], a3);
    }
    return fadd2(fadd2(a0, a1), fadd2(a2, a3));
}

// one uniform RNN sub-step for ALL 256 threads (no divergence)
__device__ __forceinline__ void substep(const ull* wX, const ull* wY, float base,
                                        const float* srcX, const float* srcY,
                                        float* dst, float* histw, const float* xwp)
{
    float xw = *xwp;                               // L1: prescaled xw[t][i]; L2: 0
    ull pX = hdot(wX, srcX);
    ull pY = hdot(wY, srcY);                       // L1: zero weights
    float p  = f2sum(fadd2(pX, pY));
    float pp = __shfl_xor_sync(0xffffffffu, p, 16);
    float s  = (base + xw) + (p + pp);             // (p+pp) same rounding on both halves
    float e, r;
    asm("ex2.approx.f32 %0, %1;" : "=f"(e) : "f"(s));       // s pre-scaled by 2/ln2
    asm("rcp.approx.f32 %0, %1;" : "=f"(r) : "f"(e + 1.0f));
    float hv = fmaf(-2.0f, r, 1.0f);               // tanh, exact saturation
    *dst   = hv;                                   // both halves: same addr, same value
    *histw = hv;
}

__global__ __launch_bounds__(NTH, 1)
void rnn_motion_kernel(const float* __restrict__ x,
                       const float* __restrict__ Wih0, const float* __restrict__ Whh0,
                       const float* __restrict__ bih0, const float* __restrict__ bhh0,
                       const float* __restrict__ Wih1, const float* __restrict__ Whh1,
                       const float* __restrict__ bih1, const float* __restrict__ bhh1,
                       const float* __restrict__ Wfc,  const float* __restrict__ bfc_g,
                       float* __restrict__ out)
{
    extern __shared__ float sm[];
    float* hist = sm + O_HIST;
    float* xs   = sm + O_XS;
    float* h1b0 = sm + O_H1;
    float* h1b1 = sm + O_H1 + HID;
    float* h2b0 = sm + O_H2;
    float* h2b1 = sm + O_H2 + HID;
    float* wfc  = sm + O_WFC;
    float* bfc  = sm + O_BFC;

    const int tid  = threadIdx.x;
    const int lane = tid & 31;
    const int lay2 = tid >> 7;                       // 0: layer1, 1: layer2
    const int i    = ((tid & 127) >> 5) * 16 + (lane & 15);
    const int joff = (lane >> 4) << 5;               // 0 or 32

    // ---- register weight loads (LDG issued early, prescaled by CSCALE) ----
    const float* wXsrc = (lay2 ? Wih1 : Whh0) + (size_t)i * HID + joff;
    const float* wYsrc = (lay2 ? Whh1 : Whh0) + (size_t)i * HID + joff;
    const float  sY    = lay2 ? CSCALE : 0.0f;       // layer1: wY == 0
    ull wX[16], wY[16];
    #pragma unroll
    for (int q = 0; q < 16; ++q) {
        float2 a = reinterpret_cast<const float2*>(wXsrc)[q];
        float2 b = reinterpret_cast<const float2*>(wYsrc)[q];
        wX[q] = pack2(a.x * CSCALE, a.y * CSCALE);
        wY[q] = pack2(b.x * sY,     b.y * sY);
    }
    const float base = lay2 ? (bih1[i] + bhh1[i]) * CSCALE : 0.0f;

    // ---- prologue A: gather x[:, B-1, :], fc weights, zero state ----
    for (int e = tid; e < SEQ*INDIM; e += NTH) {
        int t = e / INDIM, k = e % INDIM;
        xs[e] = x[((size_t)t * BATCH + (BATCH - 1)) * INDIM + k];
    }
    for (int e = tid; e < OUTD*HID; e += NTH) wfc[e] = Wfc[e];
    if (tid < OUTD) bfc[tid] = bfc_g[tid];
    for (int e = tid; e < 6*HID; e += NTH) h1b0[e] = 0.0f;      // h1,h2,zrow,trash
    for (int e = tid; e < HID;   e += NTH) hist[SEQ*HID + e] = 0.0f;  // dummy row
    __syncthreads();

    // ---- prologue B: xw[t][i] = (x_t . Wih0[i] + b_ih0[i] + b_hh0[i]) * CSCALE ----
    {
        const int ii = tid & 63;
        float wi[INDIM];
        #pragma unroll
        for (int k = 0; k < INDIM; ++k) wi[k] = Wih0[ii*INDIM + k] * CSCALE;
        const float bb = (bih0[ii] + bhh0[ii]) * CSCALE;
        for (int t = tid >> 6; t < SEQ; t += NTH/HID) {
            float s = bb;
            #pragma unroll
            for (int k = 0; k < INDIM; ++k) s += xs[t*INDIM + k] * wi[k];
            hist[t*HID + ii] = s;
        }
    }
    __syncthreads();

    // ---- per-thread data plumbing (all divergence resolved here, via SEL) ----
    const float* srcX_A = h1b0 + joff;                          // both layers read h1[t-1]
    const float* srcY_A = (lay2 ? h2b1 : h1b0) + joff;
    float*       dst_A  = (lay2 ? h2b0 : h1b1) + i;
    const float* srcX_B = h1b1 + joff;
    const float* srcY_B = (lay2 ? h2b0 : h1b1) + joff;
    float*       dst_B  = (lay2 ? h2b1 : h1b0) + i;

    const float* xwp = (lay2 ? sm + O_ZROW : hist) + i;         // L2 reads zeros
    const int xw_str = lay2 ? 0 : HID;
    float* histw = (lay2 ? hist : hist + SEQ*HID) + i;          // L1 -> dummy row
    const int hw_str = lay2 ? HID : 0;

    // ---- step 0 (B-shape): L1: h1[0]=tanh(xw[0]); L2 writes to trash ----
    {
        float* dst0 = (lay2 ? sm + O_TRASH : h1b0) + i;
        float* hw0  = (lay2 ? sm + O_TRASH : hist + SEQ*HID) + i;
        substep(wX, wY, base, h1b1 + joff, (lay2 ? h2b0 : h1b1) + joff, dst0, hw0, xwp);
        xwp += xw_str;
    }
    __syncthreads();

    // ---- main scan: 256 x (2 steps), branch-free bodies ----
    for (int k = 0; k < SEQ/2; ++k) {
        // step t = 2k+1: L1 h1[t]: h1b0->h1b1 ; L2 h2[t-1]: (h1b0,h2b1)->h2b0, hist[2k]
        substep(wX, wY, base, srcX_A, srcY_A, dst_A, histw, xwp);
        xwp += xw_str; histw += hw_str;
        __syncthreads();
        // step t+1 = 2k+2: L1 h1[t+1]: h1b1->h1b0 ; L2 h2[t]: (h1b1,h2b0)->h2b1, hist[2k+1]
        substep(wX, wY, base, srcX_B, srcY_B, dst_B, histw, xwp);
        xwp += xw_str; histw += hw_str;
        __syncthreads();
    }
    // (final L1 iteration consumed the zeroed dummy xw row; its output is never read)

    // ---- epilogue: out[t][o] = h2[t] . Wfc[o] + b_fc[o] ----
    for (int n = tid; n < SEQ*OUTD; n += NTH) {
        const int t = n / OUTD, o = n % OUTD;
        const float4* h4 = reinterpret_cast<const float4*>(hist + t*HID);
        const float4* w4 = reinterpret_cast<const float4*>(wfc + o*HID);
        float s0 = bfc[o], s1 = 0.f, s2 = 0.f, s3 = 0.f;
        #pragma unroll
        for (int q = 0; q < HID/4; ++q) {
            float4 h = h4[q], w = w4[q];
            s0 = fmaf(h.x, w.x, s0);
            s1 = fmaf(h.y, w.y, s1);
            s2 = fmaf(h.z, w.z, s2);
            s3 = fmaf(h.w, w.w, s3);
        }
        out[n] = (s0 + s1) + (s2 + s3);
    }
}

extern "C" void kernel_launch(void* const* d_in, const int* in_sizes, int n_in,
                              void* d_out, int out_size) {
    (void)in_sizes; (void)n_in; (void)out_size;
    const float* x    = (const float*)d_in[0];
    const float* Wih0 = (const float*)d_in[1];
    const float* Whh0 = (const float*)d_in[2];
    const float* bih0 = (const float*)d_in[3];
    const float* bhh0 = (const float*)d_in[4];
    const float* Wih1 = (const float*)d_in[5];
    const float* Whh1 = (const float*)d_in[6];
    const float* bih1 = (const float*)d_in[7];
    const float* bhh1 = (const float*)d_in[8];
    const float* Wfc  = (const float*)d_in[9];
    const float* bfc  = (const float*)d_in[10];
    float* out = (float*)d_out;

    cudaFuncSetAttribute(rnn_motion_kernel,
                         cudaFuncAttributeMaxDynamicSharedMemorySize, SM_BYTES);
    rnn_motion_kernel<<<1, NTH, SM_BYTES>>>(
        x, Wih0, Whh0, bih0, bhh0, Wih1, Whh1, bih1, bhh1, Wfc, bfc, out);
}

// round 4
// speedup vs baseline: 1.5003x; 1.5003x over previous
#include <cuda_runtime.h>
#include <cstddef>

#define SEQ   512
#define BATCH 4096
#define INDIM 9
#define HID   64
#define OUTD  10
#define NTH   128
#define CSCALE 2.885390081777927f      // 2/ln2
#define WSCALE (-2.0f * CSCALE)

// shared memory float offsets (all 16B aligned)
#define O_HIST  0                          // (SEQ+2)*HID : xw' rows -> r2 history; rows 512,513 dummy
#define O_XS    (O_HIST + (SEQ+2)*HID)     // SEQ*INDIM
#define O_R1    (O_XS + SEQ*INDIM)         // 2*HID
#define O_R2    (O_R1 + 2*HID)             // 2*HID
#define O_PI    (O_R2 + 2*HID)             // 2*HID*2  (64 ull per parity)
#define O_RS1   (O_PI + 4*HID)             // HID
#define O_WFC   (O_RS1 + HID)              // OUTD*HID (scaled by -2)
#define O_BFC   (O_WFC + OUTD*HID)         // 16
#define SM_FLOATS (O_BFC + 16)
#define SM_BYTES  (SM_FLOATS * 4)

typedef unsigned long long ull;

__device__ __forceinline__ ull ffma2(ull a, ull b, ull c) {
    ull d; asm("fma.rn.f32x2 %0, %1, %2, %3;" : "=l"(d) : "l"(a), "l"(b), "l"(c));
    return d;
}
__device__ __forceinline__ ull fadd2(ull a, ull b) {
    ull d; asm("add.rn.f32x2 %0, %1, %2;" : "=l"(d) : "l"(a), "l"(b));
    return d;
}
__device__ __forceinline__ float f2sum(ull a) {
    float2 f = *reinterpret_cast<float2*>(&a);
    return f.x + f.y;
}
__device__ __forceinline__ ull pack2(float x, float y) {
    ull r; asm("mov.b64 %0, {%1,%2};" : "=l"(r) : "f"(x), "f"(y));
    return r;
}
// r = 1/(e^{2s}+1), where in = C*s (C = 2/ln2). tanh(s) = 1 - 2r.
__device__ __forceinline__ float sig_r(float in) {
    float e, r;
    asm("ex2.approx.f32 %0, %1;" : "=f"(e) : "f"(in));
    asm("rcp.approx.f32 %0, %1;" : "=f"(r) : "f"(e + 1.0f));
    return r;
}
#define BAR128() asm volatile("bar.sync 0, 128;" ::: "memory")

// layer1 body: dual 64-dot sharing one LDS stream.
//  s1 = xw' + w1 . r1src  -> r1dst = sig_r(s1)
//  pI = wi2 . r1src       -> *pidst (unreduced f32x2)
__device__ __forceinline__ void l1_body(const ull* __restrict__ w1,
                                        const ull* __restrict__ wi2,
                                        const float* __restrict__ r1src, float xw,
                                        float* __restrict__ r1dst,
                                        ull* __restrict__ pidst) {
    const ulonglong2* hp = reinterpret_cast<const ulonglong2*>(r1src);
    ull a[8], b[8];
    #pragma unroll
    for (int q = 0; q < 8; ++q) { a[q] = 0ull; b[q] = 0ull; }
    #pragma unroll
    for (int q = 0; q < 8; ++q) {
        ulonglong2 u = hp[2*q], v = hp[2*q+1];
        const int o = (q & 1) * 4;
        a[o+0] = ffma2(u.x, w1[4*q+0], a[o+0]);
        a[o+1] = ffma2(u.y, w1[4*q+1], a[o+1]);
        a[o+2] = ffma2(v.x, w1[4*q+2], a[o+2]);
        a[o+3] = ffma2(v.y, w1[4*q+3], a[o+3]);
        b[o+0] = ffma2(u.x, wi2[4*q+0], b[o+0]);
        b[o+1] = ffma2(u.y, wi2[4*q+1], b[o+1]);
        b[o+2] = ffma2(v.x, wi2[4*q+2], b[o+2]);
        b[o+3] = ffma2(v.y, wi2[4*q+3], b[o+3]);
    }
    ull sa = fadd2(fadd2(fadd2(a[0],a[4]), fadd2(a[1],a[5])),
                   fadd2(fadd2(a[2],a[6]), fadd2(a[3],a[7])));
    float r = sig_r(f2sum(sa) + xw);
    *r1dst = r;
    ull sb = fadd2(fadd2(fadd2(b[0],b[4]), fadd2(b[1],b[5])),
                   fadd2(fadd2(b[2],b[6]), fadd2(b[3],b[7])));
    *pidst = sb;
}

// layer2 body: s2 = base2 + pI + wh . r2src -> r2 = sig_r(s2); exports to history
__device__ __forceinline__ void l2_body(const ull* __restrict__ wh,
                                        const float* __restrict__ r2src,
                                        const ull* __restrict__ pisrc, float base2,
                                        float* __restrict__ r2dst,
                                        float* __restrict__ histdst) {
    const ulonglong2* hp = reinterpret_cast<const ulonglong2*>(r2src);
    ull c[8];
    #pragma unroll
    for (int q = 0; q < 8; ++q) c[q] = 0ull;
    #pragma unroll
    for (int q = 0; q < 8; ++q) {
        ulonglong2 u = hp[2*q], v = hp[2*q+1];
        const int o = (q & 1) * 4;
        c[o+0] = ffma2(u.x, wh[4*q+0], c[o+0]);
        c[o+1] = ffma2(u.y, wh[4*q+1], c[o+1]);
        c[o+2] = ffma2(v.x, wh[4*q+2], c[o+2]);
        c[o+3] = ffma2(v.y, wh[4*q+3], c[o+3]);
    }
    ull pi = *pisrc;
    ull sc = fadd2(fadd2(fadd2(c[0],c[4]), fadd2(c[1],c[5])),
                   fadd2(fadd2(c[2],c[6]), fadd2(c[3],c[7])));
    sc = fadd2(sc, pi);
    float r = sig_r(f2sum(sc) + base2);
    *r2dst   = r;
    *histdst = r;
}

__global__ __launch_bounds__(NTH, 1)
void rnn_motion_kernel(const float* __restrict__ x,
                       const float* __restrict__ Wih0, const float* __restrict__ Whh0,
                       const float* __restrict__ bih0, const float* __restrict__ bhh0,
                       const float* __restrict__ Wih1, const float* __restrict__ Whh1,
                       const float* __restrict__ bih1, const float* __restrict__ bhh1,
                       const float* __restrict__ Wfc,  const float* __restrict__ bfc_g,
                       float* __restrict__ out)
{
    extern __shared__ float sm[];
    float* hist = sm + O_HIST;
    float* xs   = sm + O_XS;
    float* r1b  = sm + O_R1;
    float* r2b  = sm + O_R2;
    ull*   pib  = reinterpret_cast<ull*>(sm + O_PI);   // [2][64]
    float* rs1  = sm + O_RS1;
    float* wfc  = sm + O_WFC;
    float* bfc  = sm + O_BFC;

    const int tid = threadIdx.x;

    // ---- prologue A ----
    for (int e = tid; e < SEQ*INDIM; e += NTH) {
        int t = e / INDIM, k = e % INDIM;
        xs[e] = x[((size_t)t * BATCH + (BATCH - 1)) * INDIM + k];
    }
    for (int e = tid; e < OUTD*HID; e += NTH) wfc[e] = -2.0f * Wfc[e];
    hist[SEQ*HID + tid] = 0.0f;                         // dummy rows 512,513 (128 floats)
    if (tid < HID) {
        r1b[tid] = 0.5f; r1b[HID+tid] = 0.5f;           // h = 0  <->  r = 0.5
        r2b[tid] = 0.5f; r2b[HID+tid] = 0.5f;
        // rs1[i] = rowsum(Whh0_i)
        const float4* p = reinterpret_cast<const float4*>(Whh0 + (size_t)tid * HID);
        float s = 0.f;
        #pragma unroll
        for (int q = 0; q < 16; ++q) { float4 v = p[q]; s += (v.x+v.y)+(v.z+v.w); }
        rs1[tid] = s;
    }
    if (tid < OUTD) {                                    // bfc'[o] = bfc + rowsum(Wfc_o)
        const float4* p = reinterpret_cast<const float4*>(Wfc + (size_t)tid * HID);
        float s = bfc_g[tid];
        #pragma unroll
        for (int q = 0; q < 16; ++q) { float4 v = p[q]; s += (v.x+v.y)+(v.z+v.w); }
        bfc[tid] = s;
    }
    __syncthreads();

    // ---- prologue B: xw'[t][i] = C*(x_t.Wih0_i + b_ih0 + b_hh0 + rowsum(Whh0_i)) ----
    {
        const int ii = tid & (HID-1);
        float wi[INDIM];
        #pragma unroll
        for (int k = 0; k < INDIM; ++k) wi[k] = CSCALE * Wih0[ii*INDIM + k];
        const float bb = CSCALE * (bih0[ii] + bhh0[ii] + rs1[ii]);
        for (int t = tid >> 6; t < SEQ; t += NTH/HID) {
            float s = bb;
            #pragma unroll
            for (int k = 0; k < INDIM; ++k) s += xs[t*INDIM + k] * wi[k];
            hist[t*HID + ii] = s;
        }
    }
    __syncthreads();

    // ---- pipelined scan: iterations it = 0..513, skew: L2(it) = h2[it-2] ----
    if (tid < HID) {
        // ========== layer1 warps: r1 recurrence + pI offload ==========
        const int i = tid;
        ull w1[32], wi2[32];
        {
            const float4* p = reinterpret_cast<const float4*>(Whh0 + (size_t)i * HID);
            #pragma unroll
            for (int q = 0; q < 16; ++q) {
                float4 v = p[q];
                w1[2*q]   = pack2(v.x*WSCALE, v.y*WSCALE);
                w1[2*q+1] = pack2(v.z*WSCALE, v.w*WSCALE);
            }
            const float4* p2 = reinterpret_cast<const float4*>(Wih1 + (size_t)i * HID);
            #pragma unroll
            for (int q = 0; q < 16; ++q) {
                float4 v = p2[q];
                wi2[2*q]   = pack2(v.x*WSCALE, v.y*WSCALE);
                wi2[2*q+1] = pack2(v.z*WSCALE, v.w*WSCALE);
            }
        }
        // peel it=0 (cur=0,nxt=1), it=1 (cur=1,nxt=0)
        l1_body(w1, wi2, r1b,       hist[i],       &r1b[HID+i], &pib[HID+i]);  BAR128();
        l1_body(w1, wi2, r1b + HID, hist[HID+i],   &r1b[i],     &pib[i]);      BAR128();
        // main: it = 2..513, branch-free
        const float* xwp = hist + 2*HID + i;
        #pragma unroll 1
        for (int k2 = 0; k2 < SEQ/2; ++k2) {
            l1_body(w1, wi2, r1b,       xwp[0],   &r1b[HID+i], &pib[HID+i]);   BAR128();
            l1_body(w1, wi2, r1b + HID, xwp[HID], &r1b[i],     &pib[i]);       BAR128();
            xwp += 2*HID;
        }
    } else {
        // ========== layer2 warps: r2 recurrence from pI ==========
        const int i = tid - HID;
        ull wh[32];
        float rsH = 0.f, rsI = 0.f;
        {
            const float4* p = reinterpret_cast<const float4*>(Whh1 + (size_t)i * HID);
            #pragma unroll
            for (int q = 0; q < 16; ++q) {
                float4 v = p[q];
                rsH += (v.x+v.y)+(v.z+v.w);
                wh[2*q]   = pack2(v.x*WSCALE, v.y*WSCALE);
                wh[2*q+1] = pack2(v.z*WSCALE, v.w*WSCALE);
            }
            const float4* p2 = reinterpret_cast<const float4*>(Wih1 + (size_t)i * HID);
            #pragma unroll
            for (int q = 0; q < 16; ++q) { float4 v = p2[q]; rsI += (v.x+v.y)+(v.z+v.w); }
        }
        const float base2 = CSCALE * (bih1[i] + bhh1[i] + rsI + rsH);
        BAR128(); BAR128();                       // match layer1's peel barriers
        float* hw = hist + i;
        #pragma unroll 1
        for (int k2 = 0; k2 < SEQ/2; ++k2) {
            l2_body(wh, r2b,       &pib[i],     base2, &r2b[HID+i], hw);       BAR128();
            l2_body(wh, r2b + HID, &pib[HID+i], base2, &r2b[i],     hw + HID); BAR128();
            hw += 2*HID;
        }
    }
    __syncthreads();

    // ---- epilogue: out[t][o] = bfc'[o] + sum_k r2[t][k] * (-2*Wfc[o][k]) ----
    #pragma unroll
    for (int m = 0; m < SEQ/NTH; ++m) {
        const int t = tid + NTH * m;
        const float4* h4 = reinterpret_cast<const float4*>(hist + t*HID);
        #pragma unroll
        for (int o = 0; o < OUTD; ++o) {
            const float4* w4 = reinterpret_cast<const float4*>(wfc + o*HID);
            float s0 = bfc[o], s1 = 0.f, s2 = 0.f, s3 = 0.f;
            #pragma unroll
            for (int q = 0; q < HID/4; ++q) {
                float4 h = h4[q], w = w4[q];
                s0 = fmaf(h.x, w.x, s0);
                s1 = fmaf(h.y, w.y, s1);
                s2 = fmaf(h.z, w.z, s2);
                s3 = fmaf(h.w, w.w, s3);
            }
            out[t*OUTD + o] = (s0 + s1) + (s2 + s3);
        }
    }
}

extern "C" void kernel_launch(void* const* d_in, const int* in_sizes, int n_in,
                              void* d_out, int out_size) {
    (void)in_sizes; (void)n_in; (void)out_size;
    const float* x    = (const float*)d_in[0];
    const float* Wih0 = (const float*)d_in[1];
    const float* Whh0 = (const float*)d_in[2];
    const float* bih0 = (const float*)d_in[3];
    const float* bhh0 = (const float*)d_in[4];
    const float* Wih1 = (const float*)d_in[5];
    const float* Whh1 = (const float*)d_in[6];
    const float* bih1 = (const float*)d_in[7];
    const float* bhh1 = (const float*)d_in[8];
    const float* Wfc  = (const float*)d_in[9];
    const float* bfc  = (const float*)d_in[10];
    float* out = (float*)d_out;

    cudaFuncSetAttribute(rnn_motion_kernel,
                         cudaFuncAttributeMaxDynamicSharedMemorySize, SM_BYTES);
    rnn_motion_kernel<<<1, NTH, SM_BYTES>>>(
        x, Wih0, Whh0, bih0, bhh0, Wih1, Whh1, bih1, bhh1, Wfc, bfc, out);
}